// round 10
// baseline (speedup 1.0000x reference)
#include <cuda_runtime.h>
#include <stdint.h>

// TopK masking: out = x * mask(top-64 per row), x: [16384, 4096] fp32.
//
// TWO rows per CTA (grid 8192), 256 threads, 16 floats/row/thread in regs.
// Phases fused across both rows: 8 back-to-back streaming loads, one
// histogram pass into hist[2][256], warp0/warp1 scan rows 0/1 in parallel,
// split gather+rank, streaming stores. Selection over (value desc, col asc)
// == jax.lax.top_k stable order -> bit-deterministic.
// Exact radix-256 fallback per row for any out-of-range case.

#define THREADS 256
#define FDIM 4096
#define PER_THREAD 16
#define KSEL 64u
#define TGUESS 1.9f
#define MCAP 128u

__device__ __forceinline__ unsigned int f2key(float f) {
    unsigned int b = __float_as_uint(f);
    return (b & 0x80000000u) ? ~b : (b | 0x80000000u);
}
__device__ __forceinline__ float key2f(unsigned int k) {
    return (k & 0x80000000u) ? __uint_as_float(k & 0x7FFFFFFFu)
                             : __uint_as_float(~k);
}
// deterministic bin: identical fma at every call site; candidates (v>1.9f)
// always map to g>0 (trunc==floor), non-candidates to g<0.
__device__ __forceinline__ float gmap(float v) {
    return __fmaf_rn(v, 100.0f, -190.0f);
}
__device__ __forceinline__ int vbin(float v) {
    int b = (int)gmap(v);
    return b > 255 ? 255 : b;
}

__global__ void __launch_bounds__(THREADS, 4)
topk_mask_kernel(const float* __restrict__ x, float* __restrict__ out) {
    const int t = threadIdx.x;

    __shared__ unsigned int   hist[2][256];
    __shared__ float          mvals[2][MCAP];
    __shared__ unsigned short mcols[2][MCAP];
    __shared__ unsigned int   s_total[2], s_m[2], s_B[2], s_r[2];
    __shared__ float          s_thresh[2];
    __shared__ unsigned int   s_tcol[2], s_simple[2];
    __shared__ unsigned int   s_prefix, s_kth;     // fallback scratch (serial)

    if (t == 0) { s_m[0] = 0; s_m[1] = 0; }
    hist[0][t] = 0;
    hist[1][t] = 0;

    const size_t  r0 = (size_t)blockIdx.x * 2;
    const float4* xrow0 = reinterpret_cast<const float4*>(x + r0 * FDIM);
    const float4* xrow1 = reinterpret_cast<const float4*>(x + (r0 + 1) * FDIM);
    float4*       orow0 = reinterpret_cast<float4*>(out + r0 * FDIM);
    float4*       orow1 = reinterpret_cast<float4*>(out + (r0 + 1) * FDIM);

    // ---- load both rows (streaming); vals[v*4+j] is column 4t+1024v+j ----
    float valsA[PER_THREAD], valsB[PER_THREAD];
    #pragma unroll
    for (int v = 0; v < 4; v++) {
        const float4 a = __ldcs(&xrow0[t + v * THREADS]);
        const float4 b = __ldcs(&xrow1[t + v * THREADS]);
        valsA[v*4+0] = a.x; valsA[v*4+1] = a.y; valsA[v*4+2] = a.z; valsA[v*4+3] = a.w;
        valsB[v*4+0] = b.x; valsB[v*4+1] = b.y; valsB[v*4+2] = b.z; valsB[v*4+3] = b.w;
    }
    __syncthreads();

    // ---- histogram both rows in one pass ----
    #pragma unroll
    for (int i = 0; i < PER_THREAD; i++) {
        const float a = valsA[i];
        if (a > TGUESS) atomicAdd(&hist[0][vbin(a)], 1u);
        const float b = valsB[i];
        if (b > TGUESS) atomicAdd(&hist[1][vbin(b)], 1u);
    }
    __syncthreads();

    // ---- warps 0 & 1: per-row suffix scan over 256 bins ----
    if (t < 64) {
        const int rr   = t >> 5;                 // warp 0 -> row 0, warp 1 -> row 1
        const int lane = t & 31;
        const unsigned* h = hist[rr];
        const int b0 = lane * 8;
        unsigned lsum = 0;
        #pragma unroll
        for (int j = 0; j < 8; j++) lsum += h[b0 + j];
        unsigned suf = lsum;                     // becomes sum over lanes >= lane
        #pragma unroll
        for (int d = 1; d < 32; d <<= 1) {
            const unsigned v = __shfl_down_sync(0xFFFFFFFFu, suf, d);
            if (lane + d < 32) suf += v;
        }
        if (lane == 0) s_total[rr] = suf;
        unsigned run = suf - lsum;               // count in bins of lanes > lane
        #pragma unroll
        for (int j = 7; j >= 0; j--) {
            const unsigned cnt_gt = run;
            run += h[b0 + j];
            if (cnt_gt < KSEL && run >= KSEL) { s_B[rr] = b0 + j; s_r[rr] = KSEL - cnt_gt; }
        }
    }
    __syncthreads();

    const bool fastA = (s_total[0] >= KSEL);
    const bool fastB = (s_total[1] >= KSEL);

    // ---- gather boundary-bin elements for both rows (float interval) ----
    if (fastA) {
        const float fB = (float)s_B[0], fB1 = fB + 1.0f;
        const bool topbin = (s_B[0] == 255);
        #pragma unroll
        for (int i = 0; i < PER_THREAD; i++) {
            const float g = gmap(valsA[i]);
            if (g >= fB && (g < fB1 || topbin)) {
                const unsigned p = atomicAdd(&s_m[0], 1u);
                if (p < MCAP) {
                    mvals[0][p] = valsA[i];
                    mcols[0][p] = (unsigned short)(4*t + 1024*(i>>2) + (i&3));
                }
            }
        }
    }
    if (fastB) {
        const float fB = (float)s_B[1], fB1 = fB + 1.0f;
        const bool topbin = (s_B[1] == 255);
        #pragma unroll
        for (int i = 0; i < PER_THREAD; i++) {
            const float g = gmap(valsB[i]);
            if (g >= fB && (g < fB1 || topbin)) {
                const unsigned p = atomicAdd(&s_m[1], 1u);
                if (p < MCAP) {
                    mvals[1][p] = valsB[i];
                    mcols[1][p] = (unsigned short)(4*t + 1024*(i>>2) + (i&3));
                }
            }
        }
    }
    __syncthreads();

    const bool fbA = !fastA || (s_m[0] > MCAP);
    const bool fbB = !fastB || (s_m[1] > MCAP);

    // ---- split rank: threads 0-127 row 0, threads 128-255 row 1 ----
    {
        const int rr = (t >= 128);
        const int ti = t & 127;
        const bool fb = rr ? fbB : fbA;
        const unsigned m = s_m[rr];
        if (!fb && ti < (int)m) {
            const float    c  = mvals[rr][ti];
            const unsigned cc = mcols[rr][ti];
            unsigned gt = 0, eq = 0;
            for (unsigned j = 0; j < m; j++) {
                const float    oj = mvals[rr][j];
                const unsigned oc = mcols[rr][j];
                eq += (oj == c);
                gt += (oj > c) || (oj == c && oc < cc);
            }
            if (gt == s_r[rr] - 1) {
                s_thresh[rr] = c; s_tcol[rr] = cc; s_simple[rr] = (eq == 1u);
            }
        }
    }
    __syncthreads();

    // ---- exact radix-256 fallback per row (practically never runs) ----
    #pragma unroll
    for (int rr = 0; rr < 2; rr++) {
        const bool fb = rr ? fbB : fbA;
        if (!fb) continue;                       // uniform across block
        unsigned keys[PER_THREAD];
        #pragma unroll
        for (int i = 0; i < PER_THREAD; i++)
            keys[i] = f2key(rr ? valsB[i] : valsA[i]);

        unsigned prefix = 0, kth = KSEL;
        for (int pass = 0; pass < 4; pass++) {
            const int shift = 24 - 8 * pass;
            const unsigned pmask = pass ? (0xFFFFFFFFu << (shift + 8)) : 0u;
            __syncthreads();
            hist[rr][t] = 0;
            __syncthreads();
            #pragma unroll
            for (int i = 0; i < PER_THREAD; i++) {
                if ((keys[i] & pmask) == prefix)
                    atomicAdd(&hist[rr][(keys[i] >> shift) & 0xFFu], 1u);
            }
            __syncthreads();
            if (t == 0) {
                unsigned acc = 0;
                int b = 256;
                do { b--; acc += hist[rr][b]; } while (acc < kth && b > 0);
                s_prefix = prefix | ((unsigned)b << shift);
                s_kth    = kth - (acc - hist[rr][b]);
            }
            __syncthreads();
            prefix = s_prefix;
            kth    = s_kth;
        }
        const float fv = key2f(prefix);
        // deterministic tie resolve by column: histogram ties by col>>4
        __syncthreads();
        hist[rr][t] = 0;
        if (t == 0) { s_m[rr] = 0; s_thresh[rr] = fv; s_simple[rr] = 0; }
        __syncthreads();
        #pragma unroll
        for (int i = 0; i < PER_THREAD; i++) {
            const float v = rr ? valsB[i] : valsA[i];
            if (v == fv)
                atomicAdd(&hist[rr][(4*t + 1024*(i>>2) + (i&3)) >> 4], 1u);
        }
        __syncthreads();
        if (t == 0) {
            unsigned cum = 0; int b = 0;
            while (cum + hist[rr][b] < kth && b < 255) { cum += hist[rr][b]; b++; }
            s_B[rr] = (unsigned)b;
            s_r[rr] = kth - cum;
        }
        __syncthreads();
        #pragma unroll
        for (int i = 0; i < PER_THREAD; i++) {
            const float    v   = rr ? valsB[i] : valsA[i];
            const unsigned col = 4*t + 1024*(i>>2) + (i&3);
            if (v == fv && (col >> 4) == s_B[rr]) {
                const unsigned p = atomicAdd(&s_m[rr], 1u);   // <= 16 per bin
                mcols[rr][p] = (unsigned short)col;
            }
        }
        __syncthreads();
        const unsigned m = s_m[rr];
        if (t < (int)m) {
            const unsigned myc = mcols[rr][t];
            unsigned lower = 0;
            for (unsigned j = 0; j < m; j++) lower += (mcols[rr][j] < myc);
            if (lower == s_r[rr] - 1) s_tcol[rr] = myc;       // unique writer
        }
        __syncthreads();
    }
    __syncthreads();

    const float    tvA = s_thresh[0], tvB = s_thresh[1];
    const unsigned tcA = s_tcol[0],   tcB = s_tcol[1];

    // ---- masked streaming writes (deterministic, no atomics) ----
    if (s_simple[0]) {
        #pragma unroll
        for (int v = 0; v < 4; v++) {
            float4 o;
            o.x = (valsA[v*4+0] >= tvA) ? valsA[v*4+0] : 0.0f;
            o.y = (valsA[v*4+1] >= tvA) ? valsA[v*4+1] : 0.0f;
            o.z = (valsA[v*4+2] >= tvA) ? valsA[v*4+2] : 0.0f;
            o.w = (valsA[v*4+3] >= tvA) ? valsA[v*4+3] : 0.0f;
            __stcs(&orow0[t + v * THREADS], o);
        }
    } else {
        #pragma unroll
        for (int v = 0; v < 4; v++) {
            float4 o; float* op = &o.x;
            #pragma unroll
            for (int j = 0; j < 4; j++) {
                const float    val = valsA[v*4+j];
                const unsigned col = 4*t + 1024*v + j;
                op[j] = ((val > tvA) || (val == tvA && col <= tcA)) ? val : 0.0f;
            }
            __stcs(&orow0[t + v * THREADS], o);
        }
    }
    if (s_simple[1]) {
        #pragma unroll
        for (int v = 0; v < 4; v++) {
            float4 o;
            o.x = (valsB[v*4+0] >= tvB) ? valsB[v*4+0] : 0.0f;
            o.y = (valsB[v*4+1] >= tvB) ? valsB[v*4+1] : 0.0f;
            o.z = (valsB[v*4+2] >= tvB) ? valsB[v*4+2] : 0.0f;
            o.w = (valsB[v*4+3] >= tvB) ? valsB[v*4+3] : 0.0f;
            __stcs(&orow1[t + v * THREADS], o);
        }
    } else {
        #pragma unroll
        for (int v = 0; v < 4; v++) {
            float4 o; float* op = &o.x;
            #pragma unroll
            for (int j = 0; j < 4; j++) {
                const float    val = valsB[v*4+j];
                const unsigned col = 4*t + 1024*v + j;
                op[j] = ((val > tvB) || (val == tvB && col <= tcB)) ? val : 0.0f;
            }
            __stcs(&orow1[t + v * THREADS], o);
        }
    }
}

extern "C" void kernel_launch(void* const* d_in, const int* in_sizes, int n_in,
                              void* d_out, int out_size) {
    const float* x = (const float*)d_in[0];
    float* out     = (float*)d_out;
    const int B    = in_sizes[0] / FDIM;   // 16384
    topk_mask_kernel<<<B / 2, THREADS>>>(x, out);
}

// round 11
// speedup vs baseline: 1.1597x; 1.1597x over previous
#include <cuda_runtime.h>
#include <stdint.h>

// TopK masking: out = x * mask(top-64 per row), x: [16384, 4096] fp32.
//
// One CTA per row, 256 threads, 16 floats/thread in registers (R9 structure
// — 32 regs, ~90% occupancy — plus streaming cache hints on the GMEM
// load/store: zero-reuse 512MB stream, evict-first keeps L2 clean).
// Selection over the augmented key (value desc, col asc) == jax.lax.top_k's
// stable order -> bit-deterministic output.
// Fast path (register re-scan, no compaction):
//   1) histogram-256 over (1.9, 4.46) straight from registers
//   2) warp-0 shuffle suffix-scan -> rank-64 bin + candidate total
//   3) gather boundary-bin elements via exact float-interval test (m~2-5)
//      -> exact augmented rank; detects unique-threshold rows
//   4) write: unique threshold -> single compare; ties -> full tie-break
// Exact radix-256 fallback for any out-of-range case.

#define THREADS 256
#define FDIM 4096
#define PER_THREAD 16
#define KSEL 64u
#define TGUESS 1.9f
#define MCAP 256u

__device__ __forceinline__ unsigned int f2key(float f) {
    unsigned int b = __float_as_uint(f);
    return (b & 0x80000000u) ? ~b : (b | 0x80000000u);
}
__device__ __forceinline__ float key2f(unsigned int k) {
    return (k & 0x80000000u) ? __uint_as_float(k & 0x7FFFFFFFu)
                             : __uint_as_float(~k);
}
// deterministic bin: identical fma at every call site; candidates (v>1.9f)
// always have g>0, so trunc == floor and bins form float intervals.
__device__ __forceinline__ float gmap(float v) {
    return __fmaf_rn(v, 100.0f, -190.0f);
}
__device__ __forceinline__ int vbin(float v) {
    int b = (int)gmap(v);
    return b > 255 ? 255 : b;
}

__global__ void __launch_bounds__(THREADS, 8)
topk_mask_kernel(const float* __restrict__ x, float* __restrict__ out) {
    const int row = blockIdx.x;
    const int t   = threadIdx.x;

    __shared__ unsigned int   hist[256];
    __shared__ float          mvals[MCAP];
    __shared__ unsigned short mcols[MCAP];
    __shared__ unsigned int   s_total, s_m, s_B, s_r;
    __shared__ float          s_thresh;
    __shared__ unsigned int   s_tcol, s_simple;
    __shared__ unsigned int   s_prefix, s_kth;   // fallback

    if (t == 0) s_m = 0;
    hist[t] = 0;

    const float4* xrow = reinterpret_cast<const float4*>(x + (size_t)row * FDIM);
    float4*       orow = reinterpret_cast<float4*>(out + (size_t)row * FDIM);

    // ---- streaming load; vals[v*4+j] is column (4t + 1024v + j) ----
    float vals[PER_THREAD];
    #pragma unroll
    for (int v = 0; v < 4; v++) {
        const float4 f4 = __ldcs(&xrow[t + v * THREADS]);
        vals[v * 4 + 0] = f4.x;
        vals[v * 4 + 1] = f4.y;
        vals[v * 4 + 2] = f4.z;
        vals[v * 4 + 3] = f4.w;
    }
    __syncthreads();

    // ---- pass 1: histogram candidates straight from registers ----
    #pragma unroll
    for (int i = 0; i < PER_THREAD; i++) {
        const float v = vals[i];
        if (v > TGUESS) atomicAdd(&hist[vbin(v)], 1u);
    }
    __syncthreads();

    // ---- warp 0: suffix-scan over 256 bins; find rank-KSEL bin + total ----
    if (t < 32) {
        const int b0 = t * 8;
        unsigned lsum = 0;
        #pragma unroll
        for (int j = 0; j < 8; j++) lsum += hist[b0 + j];
        unsigned suf = lsum;                      // becomes sum over lanes >= t
        #pragma unroll
        for (int d = 1; d < 32; d <<= 1) {
            const unsigned v = __shfl_down_sync(0xFFFFFFFFu, suf, d);
            if (t + d < 32) suf += v;
        }
        if (t == 0) s_total = suf;                // total candidates
        unsigned run = suf - lsum;                // count in bins of lanes > t
        #pragma unroll
        for (int j = 7; j >= 0; j--) {
            const unsigned cnt_gt = run;          // candidates in bins > b0+j
            run += hist[b0 + j];
            if (cnt_gt < KSEL && run >= KSEL) { s_B = b0 + j; s_r = KSEL - cnt_gt; }
        }
    }
    __syncthreads();

    float    tv;       // threshold value
    unsigned tcol;     // threshold column (tie-break)
    bool fast = (s_total >= KSEL);

    if (fast) {
        const int      B = (int)s_B;
        const unsigned r = s_r;                   // rank needed inside bin B
        const float  fB  = (float)B;
        const float  fB1 = fB + 1.0f;
        const bool   topbin = (B == 255);

        // ---- pass 2: gather bin-B elements via exact float interval ----
        #pragma unroll
        for (int i = 0; i < PER_THREAD; i++) {
            const float g = gmap(vals[i]);
            if (g >= fB && (g < fB1 || topbin)) {
                const unsigned p = atomicAdd(&s_m, 1u);
                if (p < MCAP) {
                    mvals[p] = vals[i];
                    mcols[p] = (unsigned short)(4 * t + 1024 * (i >> 2) + (i & 3));
                }
            }
        }
        __syncthreads();
        const unsigned m = s_m;

        if (m <= MCAP) {
            // exact augmented ranking (value desc, col asc): unique winner.
            // equal values share a bin, so eq-count here == row-wide tie count.
            if (t < (int)m) {
                const float    c  = mvals[t];
                const unsigned cc = mcols[t];
                unsigned gt = 0, eq = 0;
                for (unsigned j = 0; j < m; j++) {
                    const float    oj = mvals[j];
                    const unsigned oc = mcols[j];
                    eq += (oj == c);
                    gt += (oj > c) || (oj == c && oc < cc);
                }
                if (gt == r - 1) {
                    s_thresh = c; s_tcol = cc; s_simple = (eq == 1u);
                }
            }
            __syncthreads();
            tv   = s_thresh;
            tcol = s_tcol;
        } else {
            fast = false;   // degenerate tie pile-up in one bin
        }
    }

    if (!fast) {
        // ---- exact 4-pass radix-256 select (practically never runs) ----
        unsigned keys[PER_THREAD];
        #pragma unroll
        for (int i = 0; i < PER_THREAD; i++) keys[i] = f2key(vals[i]);

        unsigned prefix = 0, kth = KSEL;
        for (int pass = 0; pass < 4; pass++) {
            const int shift = 24 - 8 * pass;
            const unsigned pmask = pass ? (0xFFFFFFFFu << (shift + 8)) : 0u;
            __syncthreads();
            hist[t] = 0;
            __syncthreads();
            #pragma unroll
            for (int i = 0; i < PER_THREAD; i++) {
                if ((keys[i] & pmask) == prefix)
                    atomicAdd(&hist[(keys[i] >> shift) & 0xFFu], 1u);
            }
            __syncthreads();
            if (t == 0) {
                unsigned acc = 0;
                int b = 256;
                do { b--; acc += hist[b]; } while (acc < kth && b > 0);
                s_prefix = prefix | ((unsigned)b << shift);
                s_kth    = kth - (acc - hist[b]);
            }
            __syncthreads();
            prefix = s_prefix;
            kth    = s_kth;
        }
        const float fv = key2f(prefix);           // exact threshold value
        // deterministic tie resolve by column: histogram ties by col>>4
        __syncthreads();
        hist[t] = 0;
        if (t == 0) { s_m = 0; s_thresh = fv; s_simple = 0; }
        __syncthreads();
        #pragma unroll
        for (int i = 0; i < PER_THREAD; i++) {
            if (vals[i] == fv)
                atomicAdd(&hist[(4 * t + 1024 * (i >> 2) + (i & 3)) >> 4], 1u);
        }
        __syncthreads();
        if (t == 0) {   // ascending col-bin scan: find bin holding rank 'kth'
            unsigned cum = 0; int b = 0;
            while (cum + hist[b] < kth && b < 255) { cum += hist[b]; b++; }
            s_B = (unsigned)b;
            s_r = kth - cum;                      // rank within the col-bin
        }
        __syncthreads();
        #pragma unroll
        for (int i = 0; i < PER_THREAD; i++) {
            const unsigned col = 4 * t + 1024 * (i >> 2) + (i & 3);
            if (vals[i] == fv && (col >> 4) == s_B) {
                const unsigned p = atomicAdd(&s_m, 1u);   // <= 16 per bin
                mcols[p] = (unsigned short)col;
            }
        }
        __syncthreads();
        const unsigned m = s_m;
        if (t < (int)m) {                         // rank ties ascending by col
            const unsigned myc = mcols[t];
            unsigned lower = 0;
            for (unsigned j = 0; j < m; j++) lower += (mcols[j] < myc);
            if (lower == s_r - 1) s_tcol = myc;   // unique writer
        }
        __syncthreads();
        tv   = s_thresh;
        tcol = s_tcol;
    }

    // ---- masked streaming write: deterministic, no atomics ----
    if (s_simple) {
        // threshold value is unique in the row: single compare per element
        #pragma unroll
        for (int v = 0; v < 4; v++) {
            float4 o;
            o.x = (vals[v*4+0] >= tv) ? vals[v*4+0] : 0.0f;
            o.y = (vals[v*4+1] >= tv) ? vals[v*4+1] : 0.0f;
            o.z = (vals[v*4+2] >= tv) ? vals[v*4+2] : 0.0f;
            o.w = (vals[v*4+3] >= tv) ? vals[v*4+3] : 0.0f;
            __stcs(&orow[t + v * THREADS], o);
        }
    } else {
        // exact stable tie-break (value desc, col asc)
        #pragma unroll
        for (int v = 0; v < 4; v++) {
            float4 o;
            float* op = &o.x;
            #pragma unroll
            for (int j = 0; j < 4; j++) {
                const float    val = vals[v * 4 + j];
                const unsigned col = 4 * t + 1024 * v + j;
                const bool keep = (val > tv) || (val == tv && col <= tcol);
                op[j] = keep ? val : 0.0f;
            }
            __stcs(&orow[t + v * THREADS], o);
        }
    }
}

extern "C" void kernel_launch(void* const* d_in, const int* in_sizes, int n_in,
                              void* d_out, int out_size) {
    const float* x = (const float*)d_in[0];
    float* out     = (float*)d_out;
    const int B    = in_sizes[0] / FDIM;   // 16384
    topk_mask_kernel<<<B, THREADS>>>(x, out);
}